// round 2
// baseline (speedup 1.0000x reference)
#include <cuda_runtime.h>
#include <math.h>

// Problem constants
#define BQ    8192
#define DQ    1024
#define HQ    4096
#define H2Q   2048
#define DOUTQ 1024
#define EQ    8
#define GQ    512            // D/2 gate hidden
#define PAIRS (BQ * 2)       // top-2 routing -> 16384 token-expert pairs

// ---------------- scratch (device globals; no allocations allowed) ----------
__device__ float g_g[BQ * GQ];              // gate hidden [B, 512]
__device__ float g_h1[PAIRS * HQ];          // 268 MB
__device__ float g_h2[PAIRS * H2Q];         // 134 MB
__device__ float g_y [PAIRS * DOUTQ];       //  67 MB
__device__ float g_gatew[BQ * EQ];          // softmax gate weights
__device__ int   g_topidx[BQ * 2];
__device__ float g_topw [BQ * 2];
__device__ int   g_cnt[EQ];
__device__ int   g_off[EQ + 1];
__device__ int   g_cursor[EQ];
__device__ int   g_ptok[PAIRS];             // pair -> token
__device__ int   g_pidx[BQ * 2];            // (token, slot) -> pair row
__device__ float g_usage[EQ];
__device__ int   g_gate_off[1] = {0};
__device__ int   g_gate_cnt[1] = {BQ};

// ---------------- generic segmented SGEMM --------------------------------
// C[gm, 0..N) = act( A[row(gm), 0..K) @ W_e[K,N] + bias_e[N] )
// rows gm in [seg_off[e], seg_off[e]+seg_cnt[e]) for e = blockIdx.z
// row(gm) = rowmap ? rowmap[gm] : gm
// Tiles: 128x128x16, 256 threads, 8x8 per-thread register tile.
__global__ __launch_bounds__(256) void sgemm_seg(
    const float* __restrict__ A,
    const float* __restrict__ Wbase,
    const float* __restrict__ bias,
    float* __restrict__ C,
    const int* __restrict__ rowmap,
    const int* __restrict__ seg_off,
    const int* __restrict__ seg_cnt,
    int K, int N, long wstride, int relu)
{
    const int e    = blockIdx.z;
    const int mseg = seg_off[e];
    const int mend = mseg + seg_cnt[e];
    const int m0   = mseg + blockIdx.y * 128;
    if (m0 >= mend) return;
    const int n0 = blockIdx.x * 128;

    const float* W    = Wbase + (long)e * wstride;
    const float* bvec = bias + (long)e * N;

    __shared__ float Ast[16][128];   // A transposed: [k][m]
    __shared__ float Bs [16][128];   // [k][n]

    const int tid = threadIdx.x;
    const int tx  = tid & 15;        // N direction
    const int ty  = tid >> 4;        // M direction

    float acc[8][8];
#pragma unroll
    for (int m = 0; m < 8; m++)
#pragma unroll
        for (int n = 0; n < 8; n++) acc[m][n] = 0.f;

    for (int k0 = 0; k0 < K; k0 += 16) {
        // Load A tile (rows m0..m0+127, cols k0..k0+15) with gather, store transposed
#pragma unroll
        for (int i = 0; i < 2; i++) {
            int q  = tid + i * 256;      // float4 index (512 total)
            int r  = q >> 2;             // row in tile (4 f4 per 16-col row)
            int c4 = q & 3;
            int gm = m0 + r;
            float4 v = make_float4(0.f, 0.f, 0.f, 0.f);
            if (gm < mend) {
                int src = rowmap ? rowmap[gm] : gm;
                v = *reinterpret_cast<const float4*>(A + (long)src * K + k0 + c4 * 4);
            }
            Ast[c4 * 4 + 0][r] = v.x;
            Ast[c4 * 4 + 1][r] = v.y;
            Ast[c4 * 4 + 2][r] = v.z;
            Ast[c4 * 4 + 3][r] = v.w;
        }
        // Load B tile (rows k0..k0+15, cols n0..n0+127), fully coalesced
#pragma unroll
        for (int i = 0; i < 2; i++) {
            int q  = tid + i * 256;
            int r  = q >> 5;             // 32 f4 per 128-col row
            int c4 = q & 31;
            float4 v = *reinterpret_cast<const float4*>(W + (long)(k0 + r) * N + n0 + c4 * 4);
            *reinterpret_cast<float4*>(&Bs[r][c4 * 4]) = v;
        }
        __syncthreads();

#pragma unroll
        for (int kk = 0; kk < 16; kk++) {
            float4 a0 = *reinterpret_cast<const float4*>(&Ast[kk][ty * 8]);
            float4 a1 = *reinterpret_cast<const float4*>(&Ast[kk][ty * 8 + 4]);
            float4 b0 = *reinterpret_cast<const float4*>(&Bs[kk][tx * 8]);
            float4 b1 = *reinterpret_cast<const float4*>(&Bs[kk][tx * 8 + 4]);
            float ra[8] = {a0.x, a0.y, a0.z, a0.w, a1.x, a1.y, a1.z, a1.w};
            float rb[8] = {b0.x, b0.y, b0.z, b0.w, b1.x, b1.y, b1.z, b1.w};
#pragma unroll
            for (int m = 0; m < 8; m++)
#pragma unroll
                for (int n = 0; n < 8; n++) acc[m][n] = fmaf(ra[m], rb[n], acc[m][n]);
        }
        __syncthreads();
    }

#pragma unroll
    for (int m = 0; m < 8; m++) {
        int gm = m0 + ty * 8 + m;
        if (gm >= mend) continue;
        float* crow = C + (long)gm * N;
#pragma unroll
        for (int n = 0; n < 8; n++) {
            int gn = n0 + tx * 8 + n;
            float v = acc[m][n] + bvec[gn];
            if (relu) v = fmaxf(v, 0.f);
            crow[gn] = v;
        }
    }
}

// ---------------- small kernels ------------------------------------------
__global__ void k_zero()
{
    int t = threadIdx.x;
    if (t < EQ) { g_cnt[t] = 0; g_cursor[t] = 0; }
}

// gate layer 2 + softmax + top2 + renorm + routing counts (1 warp per token)
__global__ __launch_bounds__(128) void k_gate2(const float* __restrict__ Wg2,
                                               const float* __restrict__ bg2)
{
    int b    = blockIdx.x * 4 + (threadIdx.x >> 5);
    int lane = threadIdx.x & 31;
    const float* grow = g_g + (long)b * GQ;

    float acc[8] = {0, 0, 0, 0, 0, 0, 0, 0};
    for (int k = lane; k < GQ; k += 32) {
        float gv = grow[k];
        const float* w = Wg2 + k * 8;
#pragma unroll
        for (int e = 0; e < 8; e++) acc[e] = fmaf(gv, w[e], acc[e]);
    }
#pragma unroll
    for (int e = 0; e < 8; e++) {
#pragma unroll
        for (int o = 16; o; o >>= 1) acc[e] += __shfl_xor_sync(0xffffffffu, acc[e], o);
    }
    if (lane == 0) {
        float l[8], m = -1e30f;
#pragma unroll
        for (int e = 0; e < 8; e++) { l[e] = acc[e] + bg2[e]; m = fmaxf(m, l[e]); }
        float s = 0.f;
#pragma unroll
        for (int e = 0; e < 8; e++) { l[e] = expf(l[e] - m); s += l[e]; }
        float inv = 1.f / s;
#pragma unroll
        for (int e = 0; e < 8; e++) { l[e] *= inv; g_gatew[b * 8 + e] = l[e]; }
        // top-2 (first occurrence on ties, matching jax.lax.top_k)
        int i0 = 0;
#pragma unroll
        for (int e = 1; e < 8; e++) if (l[e] > l[i0]) i0 = e;
        int i1 = -1;
#pragma unroll
        for (int e = 0; e < 8; e++) {
            if (e == i0) continue;
            if (i1 < 0 || l[e] > l[i1]) i1 = e;
        }
        float w0 = l[i0], w1 = l[i1];
        float mm = fmaxf(w0, w1);
        float e0 = expf(w0 - mm), e1 = expf(w1 - mm);
        float si = 1.f / (e0 + e1);
        g_topidx[2 * b]     = i0;
        g_topidx[2 * b + 1] = i1;
        g_topw[2 * b]       = e0 * si;
        g_topw[2 * b + 1]   = e1 * si;
        atomicAdd(&g_cnt[i0], 1);
        atomicAdd(&g_cnt[i1], 1);
    }
}

__global__ void k_offsets()
{
    if (threadIdx.x == 0) {
        int s = 0;
        for (int e = 0; e < EQ; e++) { g_off[e] = s; s += g_cnt[e]; }
        g_off[EQ] = s;
    }
}

__global__ void k_scatter()
{
    int b = blockIdx.x * blockDim.x + threadIdx.x;
    if (b >= BQ) return;
#pragma unroll
    for (int s = 0; s < 2; s++) {
        int e = g_topidx[2 * b + s];
        int p = g_off[e] + atomicAdd(&g_cursor[e], 1);
        g_ptok[p]         = b;
        g_pidx[2 * b + s] = p;
    }
}

// deterministic tree reduction of gate weights -> expert usage sums
__global__ __launch_bounds__(256) void k_usage()
{
    int e = blockIdx.x, t = threadIdx.x;
    __shared__ float sh[256];
    float s = 0.f;
    for (int b = t; b < BQ; b += 256) s += g_gatew[b * 8 + e];
    sh[t] = s;
    __syncthreads();
    for (int o = 128; o; o >>= 1) {
        if (t < o) sh[t] += sh[t + o];
        __syncthreads();
    }
    if (t == 0) g_usage[e] = sh[0];
}

__global__ void k_loss(float* out, int out_size)
{
    if (threadIdx.x == 0 && out_size > BQ * DOUTQ) {
        float acc = 0.f;
        for (int e = 0; e < EQ; e++) {
            float d = g_usage[e] / (float)BQ - 1.0f / (float)EQ;
            acc += d * d;
        }
        out[BQ * DOUTQ] = acc / (float)EQ;
    }
}

__global__ __launch_bounds__(256) void k_combine(float* __restrict__ out)
{
    int b  = blockIdx.x;
    int p0 = g_pidx[2 * b], p1 = g_pidx[2 * b + 1];
    float w0 = g_topw[2 * b], w1 = g_topw[2 * b + 1];
    const float* y0 = g_y + (long)p0 * DOUTQ;
    const float* y1 = g_y + (long)p1 * DOUTQ;
    float* o = out + (long)b * DOUTQ;
    for (int d = threadIdx.x; d < DOUTQ; d += 256)
        o[d] = w0 * y0[d] + w1 * y1[d];
}

// ---------------- launch --------------------------------------------------
extern "C" void kernel_launch(void* const* d_in, const int* in_sizes, int n_in,
                              void* d_out, int out_size)
{
    const float* x   = (const float*)d_in[0];
    const float* W1  = (const float*)d_in[1];
    const float* b1  = (const float*)d_in[2];
    const float* W2  = (const float*)d_in[3];
    const float* b2  = (const float*)d_in[4];
    const float* W3  = (const float*)d_in[5];
    const float* b3  = (const float*)d_in[6];
    const float* Wg1 = (const float*)d_in[7];
    const float* bg1 = (const float*)d_in[8];
    const float* Wg2 = (const float*)d_in[9];
    const float* bg2 = (const float*)d_in[10];
    float* out = (float*)d_out;

    float *p_g, *p_h1, *p_h2, *p_y;
    int *p_goff, *p_gcnt, *p_off, *p_cnt, *p_ptok;
    cudaGetSymbolAddress((void**)&p_g,    g_g);
    cudaGetSymbolAddress((void**)&p_h1,   g_h1);
    cudaGetSymbolAddress((void**)&p_h2,   g_h2);
    cudaGetSymbolAddress((void**)&p_y,    g_y);
    cudaGetSymbolAddress((void**)&p_goff, g_gate_off);
    cudaGetSymbolAddress((void**)&p_gcnt, g_gate_cnt);
    cudaGetSymbolAddress((void**)&p_off,  g_off);
    cudaGetSymbolAddress((void**)&p_cnt,  g_cnt);
    cudaGetSymbolAddress((void**)&p_ptok, g_ptok);

    k_zero<<<1, 32>>>();

    // gate layer 1: g = relu(x @ Wg1 + bg1)   [8192 x 512], K=1024
    {
        dim3 grid(GQ / 128, BQ / 128, 1);
        sgemm_seg<<<grid, 256>>>(x, Wg1, bg1, p_g, nullptr, p_goff, p_gcnt,
                                 DQ, GQ, 0L, 1);
    }
    k_gate2<<<BQ / 4, 128>>>(Wg2, bg2);
    k_offsets<<<1, 32>>>();
    k_scatter<<<BQ / 256, 256>>>();
    k_usage<<<EQ, 256>>>();
    k_loss<<<1, 32>>>(out, out_size);

    // expert layer 1: h1 = relu(gather(x) @ W1[e] + b1[e])   K=1024, N=4096
    {
        dim3 grid(HQ / 128, PAIRS / 128, EQ);
        sgemm_seg<<<grid, 256>>>(x, W1, b1, p_h1, p_ptok, p_off, p_cnt,
                                 DQ, HQ, (long)DQ * HQ, 1);
    }
    // expert layer 2: h2 = relu(h1 @ W2[e] + b2[e])   K=4096, N=2048
    {
        dim3 grid(H2Q / 128, PAIRS / 128, EQ);
        sgemm_seg<<<grid, 256>>>(p_h1, W2, b2, p_h2, nullptr, p_off, p_cnt,
                                 HQ, H2Q, (long)HQ * H2Q, 1);
    }
    // expert layer 3: y = h2 @ W3[e] + b3[e]   K=2048, N=1024
    {
        dim3 grid(DOUTQ / 128, PAIRS / 128, EQ);
        sgemm_seg<<<grid, 256>>>(p_h2, W3, b3, p_y, nullptr, p_off, p_cnt,
                                 H2Q, DOUTQ, (long)H2Q * DOUTQ, 0);
    }
    k_combine<<<BQ, 256>>>(out);
}

// round 6
// speedup vs baseline: 1.9728x; 1.9728x over previous
#include <cuda_runtime.h>
#include <cuda_bf16.h>
#include <math.h>
#include <stdint.h>

// Problem constants
#define BQ    8192
#define DQ    1024
#define HQ    4096
#define H2Q   2048
#define DOUTQ 1024
#define EQ    8
#define GQ    512
#define PAIRS (BQ * 2)

// ---------------- scratch (device globals) ---------------------------------
__device__ float g_g[BQ * GQ];
__device__ float g_h1[PAIRS * HQ];
__device__ float g_h2[PAIRS * H2Q];
__device__ float g_y [PAIRS * DOUTQ];
__device__ float g_gatew[BQ * EQ];
__device__ int   g_topidx[BQ * 2];
__device__ float g_topw [BQ * 2];
__device__ int   g_cnt[EQ];
__device__ int   g_off[EQ + 1];
__device__ int   g_cursor[EQ];
__device__ int   g_ptok[PAIRS];
__device__ int   g_pidx[BQ * 2];
__device__ float g_usage[EQ];
__device__ int   g_gate_off[1] = {0};
__device__ int   g_gate_cnt[1] = {BQ};

// ---------------- helpers ---------------------------------------------------
__device__ __forceinline__ uint32_t smem_u32(const void* p) {
    uint32_t a;
    asm("{ .reg .u64 t; cvta.to.shared.u64 t, %1; cvt.u32.u64 %0, t; }"
        : "=r"(a) : "l"(p));
    return a;
}
__device__ __forceinline__ uint32_t sw128(uint32_t off) {
    return off ^ ((off >> 3) & 0x70);
}
__device__ __forceinline__ void ldsm_x4(uint32_t* r, uint32_t addr) {
    asm volatile("ldmatrix.sync.aligned.m8n8.x4.shared.b16 {%0,%1,%2,%3}, [%4];"
                 : "=r"(r[0]), "=r"(r[1]), "=r"(r[2]), "=r"(r[3]) : "r"(addr));
}
__device__ __forceinline__ void mma_bf16(float* d, const uint32_t* a,
                                         uint32_t b0, uint32_t b1) {
    asm volatile(
        "mma.sync.aligned.m16n8k16.row.col.f32.bf16.bf16.f32 "
        "{%0,%1,%2,%3}, {%4,%5,%6,%7}, {%8,%9}, {%0,%1,%2,%3};"
        : "+f"(d[0]), "+f"(d[1]), "+f"(d[2]), "+f"(d[3])
        : "r"(a[0]), "r"(a[1]), "r"(a[2]), "r"(a[3]), "r"(b0), "r"(b1));
}
// split fp32 x into bf16 hi + bf16 lo (residual), packed pairwise
__device__ __forceinline__ void split2(float x, float y, uint32_t& hi, uint32_t& lo) {
    __nv_bfloat16 hx = __float2bfloat16(x);
    __nv_bfloat16 hy = __float2bfloat16(y);
    __nv_bfloat16 lx = __float2bfloat16(x - __bfloat162float(hx));
    __nv_bfloat16 ly = __float2bfloat16(y - __bfloat162float(hy));
    __nv_bfloat162 h2; h2.x = hx; h2.y = hy;
    __nv_bfloat162 l2; l2.x = lx; l2.y = ly;
    hi = *reinterpret_cast<uint32_t*>(&h2);
    lo = *reinterpret_cast<uint32_t*>(&l2);
}

// ---------------- 3xBF16 mma.sync segmented GEMM ----------------------------
// C[gm, n0..n0+128) = act(A[row(gm),:] @ W_e + bias_e)
// CTA tile 128x128, K-chunk 64. smem: Ah/Al [128][64] bf16, Bh/Bl [128n][64k] bf16,
// all 128B rows with SW128 swizzle. 8 warps: 4 along M (32 rows), 2 along N (64).
#define S_AH 0
#define S_AL 16384
#define S_BH 32768
#define S_BL 49152
#define SMEM_SZ 65536

__global__ __launch_bounds__(256, 2) void moe_bf16_gemm(
    const float* __restrict__ A,
    const float* __restrict__ Wbase,
    const float* __restrict__ bias,
    float* __restrict__ C,
    const int* __restrict__ rowmap,
    const int* __restrict__ seg_off,
    const int* __restrict__ seg_cnt,
    int K, int N, long wstride, int relu)
{
    extern __shared__ char smem[];
    const int e    = blockIdx.z;
    const int mseg = seg_off[e];
    const int mend = mseg + seg_cnt[e];
    const int m0   = mseg + blockIdx.y * 128;
    if (m0 >= mend) return;
    const int n0 = blockIdx.x * 128;

    const float* W    = Wbase + (long)e * wstride;
    const float* bvec = bias + (long)e * N;

    const uint32_t sb = smem_u32(smem);
    const int tid  = threadIdx.x;
    const int wid  = tid >> 5;
    const int lane = tid & 31;
    const int wm   = wid & 3;      // M warp (32 rows)
    const int wn   = wid >> 2;     // N warp (64 cols)

    float acc[16][4];              // [mt*8 + nt][4], mt<2, nt<8
#pragma unroll
    for (int i = 0; i < 16; i++)
#pragma unroll
        for (int j = 0; j < 4; j++) acc[i][j] = 0.f;

    // ldmatrix lane addressing pieces
    const int lr = ((lane >> 3) & 1) * 8 + (lane & 7);  // row within 16-row tile
    const int lc = (lane >> 4) * 16;                     // 16B col within 32B kstep

    for (int k0 = 0; k0 < K; k0 += 64) {
        // ---- load A chunk: 128 rows x 64 k (f32 -> bf16 hi/lo), SW128
#pragma unroll
        for (int i = 0; i < 8; i++) {
            int u  = tid + i * 256;       // 2048 float4 units
            int r  = u >> 4;              // 16 f4 per row
            int c4 = u & 15;
            float4 v = make_float4(0.f, 0.f, 0.f, 0.f);
            int gm = m0 + r;
            if (gm < mend) {
                int src = rowmap ? rowmap[gm] : gm;
                v = *reinterpret_cast<const float4*>(A + (long)src * K + k0 + c4 * 4);
            }
            uint32_t h0, l0, h1, l1;
            split2(v.x, v.y, h0, l0);
            split2(v.z, v.w, h1, l1);
            uint32_t sw = sw128((uint32_t)(r * 128 + c4 * 8));
            *reinterpret_cast<uint2*>(smem + S_AH + sw) = make_uint2(h0, h1);
            *reinterpret_cast<uint2*>(smem + S_AL + sw) = make_uint2(l0, l1);
        }
        // ---- load B chunk: W[k0..k0+64, n0..n0+128] -> Bt[n][k] bf16 hi/lo
#pragma unroll
        for (int i = 0; i < 8; i++) {
            int u  = tid + i * 256;       // 2048 (n, kquad) units
            int n  = u & 127;
            int kq = u >> 7;              // 16 k-quads
            const float* wp = W + (long)(k0 + kq * 4) * N + n0 + n;
            float v0 = wp[0];
            float v1 = wp[(long)N];
            float v2 = wp[(long)2 * N];
            float v3 = wp[(long)3 * N];
            uint32_t h0, l0, h1, l1;
            split2(v0, v1, h0, l0);
            split2(v2, v3, h1, l1);
            uint32_t sw = sw128((uint32_t)(n * 128 + kq * 8));
            *reinterpret_cast<uint2*>(smem + S_BH + sw) = make_uint2(h0, h1);
            *reinterpret_cast<uint2*>(smem + S_BL + sw) = make_uint2(l0, l1);
        }
        __syncthreads();

        // ---- compute: 4 k16 steps
#pragma unroll
        for (int ks = 0; ks < 4; ks++) {
            const int kb = ks * 32 + lc;  // byte col for this lane
            uint32_t ah[2][4], al[2][4], bfrag[4][4];
#pragma unroll
            for (int mt = 0; mt < 2; mt++) {
                uint32_t off = sw128((uint32_t)((wm * 32 + mt * 16 + lr) * 128 + kb));
                ldsm_x4(ah[mt], sb + S_AH + off);
                ldsm_x4(al[mt], sb + S_AL + off);
            }
#pragma unroll
            for (int nt = 0; nt < 4; nt++) {
                uint32_t off = sw128((uint32_t)((wn * 64 + nt * 16 + lr) * 128 + kb));
                ldsm_x4(bfrag[nt], sb + S_BH + off);
            }
            // ah*bh + al*bh
#pragma unroll
            for (int mt = 0; mt < 2; mt++)
#pragma unroll
                for (int nt = 0; nt < 4; nt++) {
                    mma_bf16(acc[mt * 8 + nt * 2 + 0], ah[mt], bfrag[nt][0], bfrag[nt][2]);
                    mma_bf16(acc[mt * 8 + nt * 2 + 1], ah[mt], bfrag[nt][1], bfrag[nt][3]);
                    mma_bf16(acc[mt * 8 + nt * 2 + 0], al[mt], bfrag[nt][0], bfrag[nt][2]);
                    mma_bf16(acc[mt * 8 + nt * 2 + 1], al[mt], bfrag[nt][1], bfrag[nt][3]);
                }
            // reload B lo over bfrag, then ah*bl
#pragma unroll
            for (int nt = 0; nt < 4; nt++) {
                uint32_t off = sw128((uint32_t)((wn * 64 + nt * 16 + lr) * 128 + kb));
                ldsm_x4(bfrag[nt], sb + S_BL + off);
            }
#pragma unroll
            for (int mt = 0; mt < 2; mt++)
#pragma unroll
                for (int nt = 0; nt < 4; nt++) {
                    mma_bf16(acc[mt * 8 + nt * 2 + 0], ah[mt], bfrag[nt][0], bfrag[nt][2]);
                    mma_bf16(acc[mt * 8 + nt * 2 + 1], ah[mt], bfrag[nt][1], bfrag[nt][3]);
                }
        }
        __syncthreads();
    }

    // ---- epilogue: bias + relu + store
#pragma unroll
    for (int mt = 0; mt < 2; mt++) {
#pragma unroll
        for (int nt = 0; nt < 8; nt++) {
            const float* a4 = acc[mt * 8 + nt];
            int col  = n0 + wn * 64 + nt * 8 + ((lane & 3) << 1);
            float bb0 = bvec[col], bb1 = bvec[col + 1];
            int row0 = m0 + wm * 32 + mt * 16 + (lane >> 2);
            if (row0 < mend) {
                float v0 = a4[0] + bb0, v1 = a4[1] + bb1;
                if (relu) { v0 = fmaxf(v0, 0.f); v1 = fmaxf(v1, 0.f); }
                *reinterpret_cast<float2*>(C + (long)row0 * N + col) = make_float2(v0, v1);
            }
            int row1 = row0 + 8;
            if (row1 < mend) {
                float v2 = a4[2] + bb0, v3 = a4[3] + bb1;
                if (relu) { v2 = fmaxf(v2, 0.f); v3 = fmaxf(v3, 0.f); }
                *reinterpret_cast<float2*>(C + (long)row1 * N + col) = make_float2(v2, v3);
            }
        }
    }
}

// ---------------- fp32 SGEMM (gate layer 1 only) ---------------------------
__global__ __launch_bounds__(256) void sgemm_seg(
    const float* __restrict__ A,
    const float* __restrict__ Wbase,
    const float* __restrict__ bias,
    float* __restrict__ C,
    const int* __restrict__ rowmap,
    const int* __restrict__ seg_off,
    const int* __restrict__ seg_cnt,
    int K, int N, long wstride, int relu)
{
    const int e    = blockIdx.z;
    const int mseg = seg_off[e];
    const int mend = mseg + seg_cnt[e];
    const int m0   = mseg + blockIdx.y * 128;
    if (m0 >= mend) return;
    const int n0 = blockIdx.x * 128;

    const float* W    = Wbase + (long)e * wstride;
    const float* bvec = bias + (long)e * N;

    __shared__ float Ast[16][128];
    __shared__ float Bs [16][128];

    const int tid = threadIdx.x;
    const int tx  = tid & 15;
    const int ty  = tid >> 4;

    float acc[8][8];
#pragma unroll
    for (int m = 0; m < 8; m++)
#pragma unroll
        for (int n = 0; n < 8; n++) acc[m][n] = 0.f;

    for (int k0 = 0; k0 < K; k0 += 16) {
#pragma unroll
        for (int i = 0; i < 2; i++) {
            int q  = tid + i * 256;
            int r  = q >> 2;
            int c4 = q & 3;
            int gm = m0 + r;
            float4 v = make_float4(0.f, 0.f, 0.f, 0.f);
            if (gm < mend) {
                int src = rowmap ? rowmap[gm] : gm;
                v = *reinterpret_cast<const float4*>(A + (long)src * K + k0 + c4 * 4);
            }
            Ast[c4 * 4 + 0][r] = v.x;
            Ast[c4 * 4 + 1][r] = v.y;
            Ast[c4 * 4 + 2][r] = v.z;
            Ast[c4 * 4 + 3][r] = v.w;
        }
#pragma unroll
        for (int i = 0; i < 2; i++) {
            int q  = tid + i * 256;
            int r  = q >> 5;
            int c4 = q & 31;
            float4 v = *reinterpret_cast<const float4*>(W + (long)(k0 + r) * N + n0 + c4 * 4);
            *reinterpret_cast<float4*>(&Bs[r][c4 * 4]) = v;
        }
        __syncthreads();

#pragma unroll
        for (int kk = 0; kk < 16; kk++) {
            float4 a0 = *reinterpret_cast<const float4*>(&Ast[kk][ty * 8]);
            float4 a1 = *reinterpret_cast<const float4*>(&Ast[kk][ty * 8 + 4]);
            float4 b0 = *reinterpret_cast<const float4*>(&Bs[kk][tx * 8]);
            float4 b1 = *reinterpret_cast<const float4*>(&Bs[kk][tx * 8 + 4]);
            float ra[8] = {a0.x, a0.y, a0.z, a0.w, a1.x, a1.y, a1.z, a1.w};
            float rb[8] = {b0.x, b0.y, b0.z, b0.w, b1.x, b1.y, b1.z, b1.w};
#pragma unroll
            for (int m = 0; m < 8; m++)
#pragma unroll
                for (int n = 0; n < 8; n++) acc[m][n] = fmaf(ra[m], rb[n], acc[m][n]);
        }
        __syncthreads();
    }

#pragma unroll
    for (int m = 0; m < 8; m++) {
        int gm = m0 + ty * 8 + m;
        if (gm >= mend) continue;
        float* crow = C + (long)gm * N;
#pragma unroll
        for (int n = 0; n < 8; n++) {
            int gn = n0 + tx * 8 + n;
            float v = acc[m][n] + bvec[gn];
            if (relu) v = fmaxf(v, 0.f);
            crow[gn] = v;
        }
    }
}

// ---------------- small kernels ------------------------------------------
__global__ void k_zero()
{
    int t = threadIdx.x;
    if (t < EQ) { g_cnt[t] = 0; g_cursor[t] = 0; }
}

__global__ __launch_bounds__(128) void k_gate2(const float* __restrict__ Wg2,
                                               const float* __restrict__ bg2)
{
    int b    = blockIdx.x * 4 + (threadIdx.x >> 5);
    int lane = threadIdx.x & 31;
    const float* grow = g_g + (long)b * GQ;

    float acc[8] = {0, 0, 0, 0, 0, 0, 0, 0};
    for (int k = lane; k < GQ; k += 32) {
        float gv = grow[k];
        const float* w = Wg2 + k * 8;
#pragma unroll
        for (int e = 0; e < 8; e++) acc[e] = fmaf(gv, w[e], acc[e]);
    }
#pragma unroll
    for (int e = 0; e < 8; e++) {
#pragma unroll
        for (int o = 16; o; o >>= 1) acc[e] += __shfl_xor_sync(0xffffffffu, acc[e], o);
    }
    if (lane == 0) {
        float l[8], m = -1e30f;
#pragma unroll
        for (int e = 0; e < 8; e++) { l[e] = acc[e] + bg2[e]; m = fmaxf(m, l[e]); }
        float s = 0.f;
#pragma unroll
        for (int e = 0; e < 8; e++) { l[e] = expf(l[e] - m); s += l[e]; }
        float inv = 1.f / s;
#pragma unroll
        for (int e = 0; e < 8; e++) { l[e] *= inv; g_gatew[b * 8 + e] = l[e]; }
        int i0 = 0;
#pragma unroll
        for (int e = 1; e < 8; e++) if (l[e] > l[i0]) i0 = e;
        int i1 = -1;
#pragma unroll
        for (int e = 0; e < 8; e++) {
            if (e == i0) continue;
            if (i1 < 0 || l[e] > l[i1]) i1 = e;
        }
        float w0 = l[i0], w1 = l[i1];
        float mm = fmaxf(w0, w1);
        float e0 = expf(w0 - mm), e1 = expf(w1 - mm);
        float si = 1.f / (e0 + e1);
        g_topidx[2 * b]     = i0;
        g_topidx[2 * b + 1] = i1;
        g_topw[2 * b]       = e0 * si;
        g_topw[2 * b + 1]   = e1 * si;
        atomicAdd(&g_cnt[i0], 1);
        atomicAdd(&g_cnt[i1], 1);
    }
}

__global__ void k_offsets()
{
    if (threadIdx.x == 0) {
        int s = 0;
        for (int e = 0; e < EQ; e++) { g_off[e] = s; s += g_cnt[e]; }
        g_off[EQ] = s;
    }
}

__global__ void k_scatter()
{
    int b = blockIdx.x * blockDim.x + threadIdx.x;
    if (b >= BQ) return;
#pragma unroll
    for (int s = 0; s < 2; s++) {
        int e = g_topidx[2 * b + s];
        int p = g_off[e] + atomicAdd(&g_cursor[e], 1);
        g_ptok[p]         = b;
        g_pidx[2 * b + s] = p;
    }
}

__global__ __launch_bounds__(256) void k_usage()
{
    int e = blockIdx.x, t = threadIdx.x;
    __shared__ float sh[256];
    float s = 0.f;
    for (int b = t; b < BQ; b += 256) s += g_gatew[b * 8 + e];
    sh[t] = s;
    __syncthreads();
    for (int o = 128; o; o >>= 1) {
        if (t < o) sh[t] += sh[t + o];
        __syncthreads();
    }
    if (t == 0) g_usage[e] = sh[0];
}

__global__ void k_loss(float* out, int out_size)
{
    if (threadIdx.x == 0 && out_size > BQ * DOUTQ) {
        float acc = 0.f;
        for (int e = 0; e < EQ; e++) {
            float d = g_usage[e] / (float)BQ - 1.0f / (float)EQ;
            acc += d * d;
        }
        out[BQ * DOUTQ] = acc / (float)EQ;
    }
}

__global__ __launch_bounds__(256) void k_combine(float* __restrict__ out)
{
    int b  = blockIdx.x;
    int p0 = g_pidx[2 * b], p1 = g_pidx[2 * b + 1];
    float w0 = g_topw[2 * b], w1 = g_topw[2 * b + 1];
    const float* y0 = g_y + (long)p0 * DOUTQ;
    const float* y1 = g_y + (long)p1 * DOUTQ;
    float* o = out + (long)b * DOUTQ;
    for (int d = threadIdx.x; d < DOUTQ; d += 256)
        o[d] = w0 * y0[d] + w1 * y1[d];
}

// ---------------- launch --------------------------------------------------
extern "C" void kernel_launch(void* const* d_in, const int* in_sizes, int n_in,
                              void* d_out, int out_size)
{
    const float* x   = (const float*)d_in[0];
    const float* W1  = (const float*)d_in[1];
    const float* b1  = (const float*)d_in[2];
    const float* W2  = (const float*)d_in[3];
    const float* b2  = (const float*)d_in[4];
    const float* W3  = (const float*)d_in[5];
    const float* b3  = (const float*)d_in[6];
    const float* Wg1 = (const float*)d_in[7];
    const float* bg1 = (const float*)d_in[8];
    const float* Wg2 = (const float*)d_in[9];
    const float* bg2 = (const float*)d_in[10];
    float* out = (float*)d_out;

    float *p_g, *p_h1, *p_h2, *p_y;
    int *p_goff, *p_gcnt, *p_off, *p_cnt, *p_ptok;
    cudaGetSymbolAddress((void**)&p_g,    g_g);
    cudaGetSymbolAddress((void**)&p_h1,   g_h1);
    cudaGetSymbolAddress((void**)&p_h2,   g_h2);
    cudaGetSymbolAddress((void**)&p_y,    g_y);
    cudaGetSymbolAddress((void**)&p_goff, g_gate_off);
    cudaGetSymbolAddress((void**)&p_gcnt, g_gate_cnt);
    cudaGetSymbolAddress((void**)&p_off,  g_off);
    cudaGetSymbolAddress((void**)&p_cnt,  g_cnt);
    cudaGetSymbolAddress((void**)&p_ptok, g_ptok);

    cudaFuncSetAttribute(moe_bf16_gemm,
                         cudaFuncAttributeMaxDynamicSharedMemorySize, SMEM_SZ);

    k_zero<<<1, 32>>>();

    // gate layer 1: g = relu(x @ Wg1 + bg1)   [8192 x 512], K=1024 (fp32)
    {
        dim3 grid(GQ / 128, BQ / 128, 1);
        sgemm_seg<<<grid, 256>>>(x, Wg1, bg1, p_g, nullptr, p_goff, p_gcnt,
                                 DQ, GQ, 0L, 1);
    }
    k_gate2<<<BQ / 4, 128>>>(Wg2, bg2);
    k_offsets<<<1, 32>>>();
    k_scatter<<<BQ / 256, 256>>>();
    k_usage<<<EQ, 256>>>();
    k_loss<<<1, 32>>>(out, out_size);

    // expert layer 1: h1 = relu(gather(x) @ W1[e] + b1[e])   K=1024, N=4096
    {
        dim3 grid(HQ / 128, PAIRS / 128, EQ);
        moe_bf16_gemm<<<grid, 256, SMEM_SZ>>>(x, W1, b1, p_h1, p_ptok, p_off,
                                              p_cnt, DQ, HQ, (long)DQ * HQ, 1);
    }
    // expert layer 2: h2 = relu(h1 @ W2[e] + b2[e])   K=4096, N=2048
    {
        dim3 grid(H2Q / 128, PAIRS / 128, EQ);
        moe_bf16_gemm<<<grid, 256, SMEM_SZ>>>(p_h1, W2, b2, p_h2, nullptr,
                                              p_off, p_cnt, HQ, H2Q,
                                              (long)HQ * H2Q, 1);
    }
    // expert layer 3: y = h2 @ W3[e] + b3[e]   K=2048, N=1024
    {
        dim3 grid(DOUTQ / 128, PAIRS / 128, EQ);
        moe_bf16_gemm<<<grid, 256, SMEM_SZ>>>(p_h2, W3, b3, p_y, nullptr,
                                              p_off, p_cnt, H2Q, DOUTQ,
                                              (long)H2Q * DOUTQ, 0);
    }
    k_combine<<<BQ, 256>>>(out);
}

// round 7
// speedup vs baseline: 2.3740x; 1.2034x over previous
#include <cuda_runtime.h>
#include <cuda_bf16.h>
#include <math.h>
#include <stdint.h>

// Problem constants
#define BQ    8192
#define DQ    1024
#define HQ    4096
#define H2Q   2048
#define DOUTQ 1024
#define EQ    8
#define GQ    512
#define PAIRS (BQ * 2)

// ---------------- scratch (device globals) ---------------------------------
__device__ float g_g[BQ * GQ];
__device__ float g_y [PAIRS * DOUTQ];
__device__ float g_gatew[BQ * EQ];
__device__ int   g_topidx[BQ * 2];
__device__ float g_topw [BQ * 2];
__device__ int   g_cnt[EQ];
__device__ int   g_off[EQ + 1];
__device__ int   g_cursor[EQ];
__device__ int   g_ptok[PAIRS];
__device__ int   g_pidx[BQ * 2];
__device__ float g_usage[EQ];
__device__ int   g_gate_off[1] = {0};
__device__ int   g_gate_cnt[1] = {BQ};

// bf16 hi/lo split operands
__device__ __nv_bfloat16 g_xh[BQ * DQ];
__device__ __nv_bfloat16 g_xl[BQ * DQ];
__device__ __nv_bfloat16 g_w1h[EQ * DQ * HQ];
__device__ __nv_bfloat16 g_w1l[EQ * DQ * HQ];
__device__ __nv_bfloat16 g_w2h[EQ * HQ * H2Q];
__device__ __nv_bfloat16 g_w2l[EQ * HQ * H2Q];
__device__ __nv_bfloat16 g_w3h[EQ * H2Q * DOUTQ];
__device__ __nv_bfloat16 g_w3l[EQ * H2Q * DOUTQ];
__device__ __nv_bfloat16 g_h1h[PAIRS * HQ];
__device__ __nv_bfloat16 g_h1l[PAIRS * HQ];
__device__ __nv_bfloat16 g_h2h[PAIRS * H2Q];
__device__ __nv_bfloat16 g_h2l[PAIRS * H2Q];

// ---------------- helpers ---------------------------------------------------
__device__ __forceinline__ uint32_t smem_u32(const void* p) {
    uint32_t a;
    asm("{ .reg .u64 t; cvta.to.shared.u64 t, %1; cvt.u32.u64 %0, t; }"
        : "=r"(a) : "l"(p));
    return a;
}
__device__ __forceinline__ uint32_t sw128(uint32_t off) {
    return off ^ ((off >> 3) & 0x70);
}
__device__ __forceinline__ void ldsm_x4(uint32_t* r, uint32_t addr) {
    asm volatile("ldmatrix.sync.aligned.m8n8.x4.shared.b16 {%0,%1,%2,%3}, [%4];"
                 : "=r"(r[0]), "=r"(r[1]), "=r"(r[2]), "=r"(r[3]) : "r"(addr));
}
__device__ __forceinline__ void mma_bf16(float* d, const uint32_t* a,
                                         uint32_t b0, uint32_t b1) {
    asm volatile(
        "mma.sync.aligned.m16n8k16.row.col.f32.bf16.bf16.f32 "
        "{%0,%1,%2,%3}, {%4,%5,%6,%7}, {%8,%9}, {%0,%1,%2,%3};"
        : "+f"(d[0]), "+f"(d[1]), "+f"(d[2]), "+f"(d[3])
        : "r"(a[0]), "r"(a[1]), "r"(a[2]), "r"(a[3]), "r"(b0), "r"(b1));
}
__device__ __forceinline__ void cpa16(uint32_t d, const void* s) {
    asm volatile("cp.async.cg.shared.global [%0], [%1], 16;" :: "r"(d), "l"(s));
}
#define CP_COMMIT() asm volatile("cp.async.commit_group;" ::: "memory")
#define CP_WAIT1()  asm volatile("cp.async.wait_group 1;" ::: "memory")
#define CP_WAIT0()  asm volatile("cp.async.wait_group 0;" ::: "memory")

// ---------------- 3xBF16 pipelined segmented GEMM ---------------------------
// C[gm, n0..n0+128) = act(A[row(gm),:] @ B_e^T + bias_e)
// A: bf16 hi/lo [rows][K]; B: bf16 hi/lo [E][N][K] (pre-transposed).
// CTA tile 256Mx128N, K-chunk 64, 512 threads, 16 warps (8M x 2N), 2-stage cp.async.
#define TM 256
#define TN 128
#define TK 64
#define STG_A  32768                         // Ah bytes (256*64*2)
#define STG_B  16384                         // Bh bytes (128*64*2)
#define O_AH   0
#define O_AL   STG_A
#define O_BH   (2 * STG_A)
#define O_BL   (2 * STG_A + STG_B)
#define STG_SZ (2 * STG_A + 2 * STG_B)       // 98304
#define SMEM_SZ (2 * STG_SZ)                 // 196608

__global__ __launch_bounds__(512, 1) void moe_bf16_gemm2(
    const __nv_bfloat16* __restrict__ Ah, const __nv_bfloat16* __restrict__ Al,
    const __nv_bfloat16* __restrict__ Bh, const __nv_bfloat16* __restrict__ Bl,
    const float* __restrict__ bias,
    __nv_bfloat16* __restrict__ Ch, __nv_bfloat16* __restrict__ Cl,
    float* __restrict__ Cf,
    const int* __restrict__ rowmap,
    const int* __restrict__ seg_off,
    const int* __restrict__ seg_cnt,
    int K, int N, int relu)
{
    extern __shared__ char smem[];
    const int e    = blockIdx.z;
    const int mseg = seg_off[e];
    const int mend = mseg + seg_cnt[e];
    const int m0   = mseg + blockIdx.y * TM;
    if (m0 >= mend) return;
    const int n0 = blockIdx.x * TN;

    const long wbase = (long)e * (long)N * (long)K;
    const __nv_bfloat16* Bhe = Bh + wbase;
    const __nv_bfloat16* Ble = Bl + wbase;
    const float* bvec = bias + (long)e * N;

    const uint32_t sb = smem_u32(smem);
    const int tid  = threadIdx.x;
    const int wid  = tid >> 5;
    const int lane = tid & 31;
    const int wm   = wid & 7;      // 8 M-warps x 32 rows
    const int wn   = wid >> 3;     // 2 N-warps x 64 cols

    float acc[16][4];
#pragma unroll
    for (int i = 0; i < 16; i++)
#pragma unroll
        for (int j = 0; j < 4; j++) acc[i][j] = 0.f;

    const int lr = ((lane >> 3) & 1) * 8 + (lane & 7);
    const int lc = (lane >> 4) * 16;

    const int nk = K / TK;
    for (int kc = 0; kc <= nk; kc++) {
        // ---- issue cp.async loads for chunk kc into stage kc&1
        if (kc < nk) {
            const uint32_t base = sb + (kc & 1) * STG_SZ;
            const int kbase = kc * TK;
            // A hi+lo: 4096 16B chunks
#pragma unroll
            for (int i = 0; i < 8; i++) {
                int u    = tid + i * 512;
                int half = u >> 11;
                int v    = u & 2047;
                int r    = v >> 3;
                int c    = v & 7;
                int gm = m0 + r;
                if (gm >= mend) gm = mend - 1;     // clamp: finite dup data, rows masked at store
                int src = rowmap ? rowmap[gm] : gm;
                const __nv_bfloat16* g = (half ? Al : Ah) + (long)src * K + kbase + c * 8;
                uint32_t d = base + (half ? O_AL : O_AH) + sw128((uint32_t)(r * 128 + c * 16));
                cpa16(d, g);
            }
            // B hi+lo: 2048 16B chunks
#pragma unroll
            for (int i = 0; i < 4; i++) {
                int u    = tid + i * 512;
                int half = u >> 10;
                int v    = u & 1023;
                int r    = v >> 3;
                int c    = v & 7;
                const __nv_bfloat16* g = (half ? Ble : Bhe) + (long)(n0 + r) * K + kbase + c * 8;
                uint32_t d = base + (half ? O_BL : O_BH) + sw128((uint32_t)(r * 128 + c * 16));
                cpa16(d, g);
            }
            CP_COMMIT();
        }
        // ---- compute chunk kc-1 from stage (kc-1)&1
        if (kc > 0) {
            if (kc < nk) { CP_WAIT1(); } else { CP_WAIT0(); }
            __syncthreads();
            const uint32_t base = sb + ((kc - 1) & 1) * STG_SZ;
#pragma unroll
            for (int ks = 0; ks < 4; ks++) {
                const int kb = ks * 32 + lc;
                uint32_t ahf[2][4], alf[2][4], bfrag[4][4];
#pragma unroll
                for (int mt = 0; mt < 2; mt++) {
                    uint32_t off = sw128((uint32_t)((wm * 32 + mt * 16 + lr) * 128 + kb));
                    ldsm_x4(ahf[mt], base + O_AH + off);
                    ldsm_x4(alf[mt], base + O_AL + off);
                }
#pragma unroll
                for (int nt = 0; nt < 4; nt++) {
                    uint32_t off = sw128((uint32_t)((wn * 64 + nt * 16 + lr) * 128 + kb));
                    ldsm_x4(bfrag[nt], base + O_BH + off);
                }
#pragma unroll
                for (int mt = 0; mt < 2; mt++)
#pragma unroll
                    for (int nt = 0; nt < 4; nt++) {
                        mma_bf16(acc[mt * 8 + nt * 2 + 0], ahf[mt], bfrag[nt][0], bfrag[nt][2]);
                        mma_bf16(acc[mt * 8 + nt * 2 + 1], ahf[mt], bfrag[nt][1], bfrag[nt][3]);
                        mma_bf16(acc[mt * 8 + nt * 2 + 0], alf[mt], bfrag[nt][0], bfrag[nt][2]);
                        mma_bf16(acc[mt * 8 + nt * 2 + 1], alf[mt], bfrag[nt][1], bfrag[nt][3]);
                    }
#pragma unroll
                for (int nt = 0; nt < 4; nt++) {
                    uint32_t off = sw128((uint32_t)((wn * 64 + nt * 16 + lr) * 128 + kb));
                    ldsm_x4(bfrag[nt], base + O_BL + off);
                }
#pragma unroll
                for (int mt = 0; mt < 2; mt++)
#pragma unroll
                    for (int nt = 0; nt < 4; nt++) {
                        mma_bf16(acc[mt * 8 + nt * 2 + 0], ahf[mt], bfrag[nt][0], bfrag[nt][2]);
                        mma_bf16(acc[mt * 8 + nt * 2 + 1], ahf[mt], bfrag[nt][1], bfrag[nt][3]);
                    }
            }
            __syncthreads();
        }
    }

    // ---- epilogue: bias + relu, then either split bf16 hi/lo or fp32 store
#pragma unroll
    for (int mt = 0; mt < 2; mt++) {
#pragma unroll
        for (int nt = 0; nt < 8; nt++) {
            const float* a4 = acc[mt * 8 + nt];
            int col  = n0 + wn * 64 + nt * 8 + ((lane & 3) << 1);
            float bb0 = bvec[col], bb1 = bvec[col + 1];
            int row0 = m0 + wm * 32 + mt * 16 + (lane >> 2);
            int row1 = row0 + 8;
            float v0 = a4[0] + bb0, v1 = a4[1] + bb1;
            float v2 = a4[2] + bb0, v3 = a4[3] + bb1;
            if (relu) {
                v0 = fmaxf(v0, 0.f); v1 = fmaxf(v1, 0.f);
                v2 = fmaxf(v2, 0.f); v3 = fmaxf(v3, 0.f);
            }
            if (Cf) {
                if (row0 < mend)
                    *reinterpret_cast<float2*>(Cf + (long)row0 * N + col) = make_float2(v0, v1);
                if (row1 < mend)
                    *reinterpret_cast<float2*>(Cf + (long)row1 * N + col) = make_float2(v2, v3);
            } else {
                if (row0 < mend) {
                    __nv_bfloat162 h, l;
                    h.x = __float2bfloat16(v0); h.y = __float2bfloat16(v1);
                    l.x = __float2bfloat16(v0 - __bfloat162float(h.x));
                    l.y = __float2bfloat16(v1 - __bfloat162float(h.y));
                    *reinterpret_cast<uint32_t*>(Ch + (long)row0 * N + col) = *reinterpret_cast<uint32_t*>(&h);
                    *reinterpret_cast<uint32_t*>(Cl + (long)row0 * N + col) = *reinterpret_cast<uint32_t*>(&l);
                }
                if (row1 < mend) {
                    __nv_bfloat162 h, l;
                    h.x = __float2bfloat16(v2); h.y = __float2bfloat16(v3);
                    l.x = __float2bfloat16(v2 - __bfloat162float(h.x));
                    l.y = __float2bfloat16(v3 - __bfloat162float(h.y));
                    *reinterpret_cast<uint32_t*>(Ch + (long)row1 * N + col) = *reinterpret_cast<uint32_t*>(&h);
                    *reinterpret_cast<uint32_t*>(Cl + (long)row1 * N + col) = *reinterpret_cast<uint32_t*>(&l);
                }
            }
        }
    }
}

// ---------------- split / transpose pre-passes ------------------------------
__global__ __launch_bounds__(256) void k_splitx(const float* __restrict__ x)
{
    long i = (long)(blockIdx.x * 256 + threadIdx.x) * 4;
    if (i >= (long)BQ * DQ) return;
    float4 v = *reinterpret_cast<const float4*>(x + i);
    __nv_bfloat162 h0, l0, h1, l1;
    h0.x = __float2bfloat16(v.x); h0.y = __float2bfloat16(v.y);
    l0.x = __float2bfloat16(v.x - __bfloat162float(h0.x));
    l0.y = __float2bfloat16(v.y - __bfloat162float(h0.y));
    h1.x = __float2bfloat16(v.z); h1.y = __float2bfloat16(v.w);
    l1.x = __float2bfloat16(v.z - __bfloat162float(h1.x));
    l1.y = __float2bfloat16(v.w - __bfloat162float(h1.y));
    *reinterpret_cast<uint2*>(g_xh + i) = make_uint2(
        *reinterpret_cast<uint32_t*>(&h0), *reinterpret_cast<uint32_t*>(&h1));
    *reinterpret_cast<uint2*>(g_xl + i) = make_uint2(
        *reinterpret_cast<uint32_t*>(&l0), *reinterpret_cast<uint32_t*>(&l1));
}

// W [E][K][N] f32 -> Wh/Wl [E][N][K] bf16
__global__ __launch_bounds__(256) void k_splitw(
    const float* __restrict__ src, __nv_bfloat16* __restrict__ dh,
    __nv_bfloat16* __restrict__ dl, int K, int N)
{
    __shared__ float t[32][33];
    const int e  = blockIdx.z;
    const int n0 = blockIdx.x * 32;
    const int k0 = blockIdx.y * 32;
    const int tx = threadIdx.x & 31;
    const int ty = threadIdx.x >> 5;  // 0..7
    const float* S = src + (long)e * K * N;
    const long ob  = (long)e * N * K;
#pragma unroll
    for (int i = 0; i < 32; i += 8)
        t[ty + i][tx] = S[(long)(k0 + ty + i) * N + n0 + tx];
    __syncthreads();
#pragma unroll
    for (int i = 0; i < 32; i += 8) {
        float v = t[tx][ty + i];
        __nv_bfloat16 h = __float2bfloat16(v);
        __nv_bfloat16 l = __float2bfloat16(v - __bfloat162float(h));
        long o = ob + (long)(n0 + ty + i) * K + k0 + tx;
        dh[o] = h;
        dl[o] = l;
    }
}

// ---------------- fp32 SGEMM (gate layer 1 only) ---------------------------
__global__ __launch_bounds__(256) void sgemm_seg(
    const float* __restrict__ A,
    const float* __restrict__ Wbase,
    const float* __restrict__ bias,
    float* __restrict__ C,
    const int* __restrict__ seg_off,
    const int* __restrict__ seg_cnt,
    int K, int N, int relu)
{
    const int e    = blockIdx.z;
    const int mseg = seg_off[e];
    const int mend = mseg + seg_cnt[e];
    const int m0   = mseg + blockIdx.y * 128;
    if (m0 >= mend) return;
    const int n0 = blockIdx.x * 128;

    const float* W    = Wbase;
    const float* bvec = bias;

    __shared__ float Ast[16][128];
    __shared__ float Bs [16][128];

    const int tid = threadIdx.x;
    const int tx  = tid & 15;
    const int ty  = tid >> 4;

    float acc[8][8];
#pragma unroll
    for (int m = 0; m < 8; m++)
#pragma unroll
        for (int n = 0; n < 8; n++) acc[m][n] = 0.f;

    for (int k0 = 0; k0 < K; k0 += 16) {
#pragma unroll
        for (int i = 0; i < 2; i++) {
            int q  = tid + i * 256;
            int r  = q >> 2;
            int c4 = q & 3;
            int gm = m0 + r;
            float4 v = make_float4(0.f, 0.f, 0.f, 0.f);
            if (gm < mend)
                v = *reinterpret_cast<const float4*>(A + (long)gm * K + k0 + c4 * 4);
            Ast[c4 * 4 + 0][r] = v.x;
            Ast[c4 * 4 + 1][r] = v.y;
            Ast[c4 * 4 + 2][r] = v.z;
            Ast[c4 * 4 + 3][r] = v.w;
        }
#pragma unroll
        for (int i = 0; i < 2; i++) {
            int q  = tid + i * 256;
            int r  = q >> 5;
            int c4 = q & 31;
            float4 v = *reinterpret_cast<const float4*>(W + (long)(k0 + r) * N + n0 + c4 * 4);
            *reinterpret_cast<float4*>(&Bs[r][c4 * 4]) = v;
        }
        __syncthreads();

#pragma unroll
        for (int kk = 0; kk < 16; kk++) {
            float4 a0 = *reinterpret_cast<const float4*>(&Ast[kk][ty * 8]);
            float4 a1 = *reinterpret_cast<const float4*>(&Ast[kk][ty * 8 + 4]);
            float4 b0 = *reinterpret_cast<const float4*>(&Bs[kk][tx * 8]);
            float4 b1 = *reinterpret_cast<const float4*>(&Bs[kk][tx * 8 + 4]);
            float ra[8] = {a0.x, a0.y, a0.z, a0.w, a1.x, a1.y, a1.z, a1.w};
            float rb[8] = {b0.x, b0.y, b0.z, b0.w, b1.x, b1.y, b1.z, b1.w};
#pragma unroll
            for (int m = 0; m < 8; m++)
#pragma unroll
                for (int n = 0; n < 8; n++) acc[m][n] = fmaf(ra[m], rb[n], acc[m][n]);
        }
        __syncthreads();
    }

#pragma unroll
    for (int m = 0; m < 8; m++) {
        int gm = m0 + ty * 8 + m;
        if (gm >= mend) continue;
        float* crow = C + (long)gm * N;
#pragma unroll
        for (int n = 0; n < 8; n++) {
            int gn = n0 + tx * 8 + n;
            float v = acc[m][n] + bvec[gn];
            if (relu) v = fmaxf(v, 0.f);
            crow[gn] = v;
        }
    }
}

// ---------------- small kernels ------------------------------------------
__global__ void k_zero()
{
    int t = threadIdx.x;
    if (t < EQ) { g_cnt[t] = 0; g_cursor[t] = 0; }
}

__global__ __launch_bounds__(128) void k_gate2(const float* __restrict__ Wg2,
                                               const float* __restrict__ bg2)
{
    int b    = blockIdx.x * 4 + (threadIdx.x >> 5);
    int lane = threadIdx.x & 31;
    const float* grow = g_g + (long)b * GQ;

    float acc[8] = {0, 0, 0, 0, 0, 0, 0, 0};
    for (int k = lane; k < GQ; k += 32) {
        float gv = grow[k];
        const float* w = Wg2 + k * 8;
#pragma unroll
        for (int e = 0; e < 8; e++) acc[e] = fmaf(gv, w[e], acc[e]);
    }
#pragma unroll
    for (int e = 0; e < 8; e++) {
#pragma unroll
        for (int o = 16; o; o >>= 1) acc[e] += __shfl_xor_sync(0xffffffffu, acc[e], o);
    }
    if (lane == 0) {
        float l[8], m = -1e30f;
#pragma unroll
        for (int e = 0; e < 8; e++) { l[e] = acc[e] + bg2[e]; m = fmaxf(m, l[e]); }
        float s = 0.f;
#pragma unroll
        for (int e = 0; e < 8; e++) { l[e] = expf(l[e] - m); s += l[e]; }
        float inv = 1.f / s;
#pragma unroll
        for (int e = 0; e < 8; e++) { l[e] *= inv; g_gatew[b * 8 + e] = l[e]; }
        int i0 = 0;
#pragma unroll
        for (int e = 1; e < 8; e++) if (l[e] > l[i0]) i0 = e;
        int i1 = -1;
#pragma unroll
        for (int e = 0; e < 8; e++) {
            if (e == i0) continue;
            if (i1 < 0 || l[e] > l[i1]) i1 = e;
        }
        float w0 = l[i0], w1 = l[i1];
        float mm = fmaxf(w0, w1);
        float e0 = expf(w0 - mm), e1 = expf(w1 - mm);
        float si = 1.f / (e0 + e1);
        g_topidx[2 * b]     = i0;
        g_topidx[2 * b + 1] = i1;
        g_topw[2 * b]       = e0 * si;
        g_topw[2 * b + 1]   = e1 * si;
        atomicAdd(&g_cnt[i0], 1);
        atomicAdd(&g_cnt[i1], 1);
    }
}

__global__ void k_offsets()
{
    if (threadIdx.x == 0) {
        int s = 0;
        for (int e = 0; e < EQ; e++) { g_off[e] = s; s += g_cnt[e]; }
        g_off[EQ] = s;
    }
}

__global__ void k_scatter()
{
    int b = blockIdx.x * blockDim.x + threadIdx.x;
    if (b >= BQ) return;
#pragma unroll
    for (int s = 0; s < 2; s++) {
        int e = g_topidx[2 * b + s];
        int p = g_off[e] + atomicAdd(&g_cursor[e], 1);
        g_ptok[p]         = b;
        g_pidx[2 * b + s] = p;
    }
}

__global__ __launch_bounds__(256) void k_usage()
{
    int e = blockIdx.x, t = threadIdx.x;
    __shared__ float sh[256];
    float s = 0.f;
    for (int b = t; b < BQ; b += 256) s += g_gatew[b * 8 + e];
    sh[t] = s;
    __syncthreads();
    for (int o = 128; o; o >>= 1) {
        if (t < o) sh[t] += sh[t + o];
        __syncthreads();
    }
    if (t == 0) g_usage[e] = sh[0];
}

__global__ void k_loss(float* out, int out_size)
{
    if (threadIdx.x == 0 && out_size > BQ * DOUTQ) {
        float acc = 0.f;
        for (int e = 0; e < EQ; e++) {
            float d = g_usage[e] / (float)BQ - 1.0f / (float)EQ;
            acc += d * d;
        }
        out[BQ * DOUTQ] = acc / (float)EQ;
    }
}

__global__ __launch_bounds__(256) void k_combine(float* __restrict__ out)
{
    int b  = blockIdx.x;
    int p0 = g_pidx[2 * b], p1 = g_pidx[2 * b + 1];
    float w0 = g_topw[2 * b], w1 = g_topw[2 * b + 1];
    const float* y0 = g_y + (long)p0 * DOUTQ;
    const float* y1 = g_y + (long)p1 * DOUTQ;
    float* o = out + (long)b * DOUTQ;
    for (int d = threadIdx.x; d < DOUTQ; d += 256)
        o[d] = w0 * y0[d] + w1 * y1[d];
}

// ---------------- launch --------------------------------------------------
extern "C" void kernel_launch(void* const* d_in, const int* in_sizes, int n_in,
                              void* d_out, int out_size)
{
    const float* x   = (const float*)d_in[0];
    const float* W1  = (const float*)d_in[1];
    const float* b1  = (const float*)d_in[2];
    const float* W2  = (const float*)d_in[3];
    const float* b2  = (const float*)d_in[4];
    const float* W3  = (const float*)d_in[5];
    const float* b3  = (const float*)d_in[6];
    const float* Wg1 = (const float*)d_in[7];
    const float* bg1 = (const float*)d_in[8];
    const float* Wg2 = (const float*)d_in[9];
    const float* bg2 = (const float*)d_in[10];
    float* out = (float*)d_out;

    float* p_g;
    float* p_y;
    int *p_goff, *p_gcnt, *p_off, *p_cnt, *p_ptok;
    __nv_bfloat16 *p_xh, *p_xl, *p_w1h, *p_w1l, *p_w2h, *p_w2l, *p_w3h, *p_w3l;
    __nv_bfloat16 *p_h1h, *p_h1l, *p_h2h, *p_h2l;
    cudaGetSymbolAddress((void**)&p_g,    g_g);
    cudaGetSymbolAddress((void**)&p_y,    g_y);
    cudaGetSymbolAddress((void**)&p_goff, g_gate_off);
    cudaGetSymbolAddress((void**)&p_gcnt, g_gate_cnt);
    cudaGetSymbolAddress((void**)&p_off,  g_off);
    cudaGetSymbolAddress((void**)&p_cnt,  g_cnt);
    cudaGetSymbolAddress((void**)&p_ptok, g_ptok);
    cudaGetSymbolAddress((void**)&p_xh,   g_xh);
    cudaGetSymbolAddress((void**)&p_xl,   g_xl);
    cudaGetSymbolAddress((void**)&p_w1h,  g_w1h);
    cudaGetSymbolAddress((void**)&p_w1l,  g_w1l);
    cudaGetSymbolAddress((void**)&p_w2h,  g_w2h);
    cudaGetSymbolAddress((void**)&p_w2l,  g_w2l);
    cudaGetSymbolAddress((void**)&p_w3h,  g_w3h);
    cudaGetSymbolAddress((void**)&p_w3l,  g_w3l);
    cudaGetSymbolAddress((void**)&p_h1h,  g_h1h);
    cudaGetSymbolAddress((void**)&p_h1l,  g_h1l);
    cudaGetSymbolAddress((void**)&p_h2h,  g_h2h);
    cudaGetSymbolAddress((void**)&p_h2l,  g_h2l);

    cudaFuncSetAttribute(moe_bf16_gemm2,
                         cudaFuncAttributeMaxDynamicSharedMemorySize, SMEM_SZ);

    k_zero<<<1, 32>>>();

    // pre-split x and weights (hi/lo bf16, W transposed to [E][N][K])
    k_splitx<<<(BQ * DQ / 4 + 255) / 256, 256>>>(x);
    {
        dim3 g1(HQ / 32, DQ / 32, EQ);
        k_splitw<<<g1, 256>>>(W1, p_w1h, p_w1l, DQ, HQ);
        dim3 g2(H2Q / 32, HQ / 32, EQ);
        k_splitw<<<g2, 256>>>(W2, p_w2h, p_w2l, HQ, H2Q);
        dim3 g3(DOUTQ / 32, H2Q / 32, EQ);
        k_splitw<<<g3, 256>>>(W3, p_w3h, p_w3l, H2Q, DOUTQ);
    }

    // gate: g = relu(x @ Wg1 + bg1) then layer2 + softmax + top2 + routing
    {
        dim3 grid(GQ / 128, BQ / 128, 1);
        sgemm_seg<<<grid, 256>>>(x, Wg1, bg1, p_g, p_goff, p_gcnt, DQ, GQ, 1);
    }
    k_gate2<<<BQ / 4, 128>>>(Wg2, bg2);
    k_offsets<<<1, 32>>>();
    k_scatter<<<BQ / 256, 256>>>();
    k_usage<<<EQ, 256>>>();
    k_loss<<<1, 32>>>(out, out_size);

    // expert layer 1: h1 = relu(gather(x) @ W1[e] + b1[e])  K=1024, N=4096
    {
        dim3 grid(HQ / TN, PAIRS / TM, EQ);
        moe_bf16_gemm2<<<grid, 512, SMEM_SZ>>>(
            p_xh, p_xl, p_w1h, p_w1l, b1, p_h1h, p_h1l, nullptr,
            p_ptok, p_off, p_cnt, DQ, HQ, 1);
    }
    // expert layer 2: h2 = relu(h1 @ W2[e] + b2[e])  K=4096, N=2048
    {
        dim3 grid(H2Q / TN, PAIRS / TM, EQ);
        moe_bf16_gemm2<<<grid, 512, SMEM_SZ>>>(
            p_h1h, p_h1l, p_w2h, p_w2l, b2, p_h2h, p_h2l, nullptr,
            nullptr, p_off, p_cnt, HQ, H2Q, 1);
    }
    // expert layer 3: y = h2 @ W3[e] + b3[e]  K=2048, N=1024
    {
        dim3 grid(DOUTQ / TN, PAIRS / TM, EQ);
        moe_bf16_gemm2<<<grid, 512, SMEM_SZ>>>(
            p_h2h, p_h2l, p_w3h, p_w3l, b3, nullptr, nullptr, p_y,
            nullptr, p_off, p_cnt, H2Q, DOUTQ, 0);
    }
    k_combine<<<BQ, 256>>>(out);
}

// round 8
// speedup vs baseline: 2.5235x; 1.0629x over previous
#include <cuda_runtime.h>
#include <cuda_bf16.h>
#include <math.h>
#include <stdint.h>

// Problem constants
#define BQ    8192
#define DQ    1024
#define HQ    4096
#define H2Q   2048
#define DOUTQ 1024
#define EQ    8
#define GQ    512
#define PAIRS (BQ * 2)

// ---------------- scratch (device globals) ---------------------------------
__device__ float g_g[BQ * GQ];
__device__ float g_y [PAIRS * DOUTQ];
__device__ float g_gatew[BQ * EQ];
__device__ int   g_topidx[BQ * 2];
__device__ float g_topw [BQ * 2];
__device__ int   g_cnt[EQ];
__device__ int   g_off[EQ + 1];
__device__ int   g_cursor[EQ];
__device__ int   g_ptok[PAIRS];
__device__ int   g_pidx[BQ * 2];
__device__ float g_usage[EQ];
__device__ int   g_gate_off[1] = {0};
__device__ int   g_gate_cnt[1] = {BQ};

// bf16 hi/lo split operands
__device__ __nv_bfloat16 g_xh[BQ * DQ];
__device__ __nv_bfloat16 g_xl[BQ * DQ];
__device__ __nv_bfloat16 g_w1h[EQ * DQ * HQ];
__device__ __nv_bfloat16 g_w1l[EQ * DQ * HQ];
__device__ __nv_bfloat16 g_w2h[EQ * HQ * H2Q];
__device__ __nv_bfloat16 g_w2l[EQ * HQ * H2Q];
__device__ __nv_bfloat16 g_w3h[EQ * H2Q * DOUTQ];
__device__ __nv_bfloat16 g_w3l[EQ * H2Q * DOUTQ];
__device__ __nv_bfloat16 g_h1h[PAIRS * HQ];
__device__ __nv_bfloat16 g_h1l[PAIRS * HQ];
__device__ __nv_bfloat16 g_h2h[PAIRS * H2Q];
__device__ __nv_bfloat16 g_h2l[PAIRS * H2Q];

// ---------------- helpers ---------------------------------------------------
__device__ __forceinline__ uint32_t smem_u32(const void* p) {
    uint32_t a;
    asm("{ .reg .u64 t; cvta.to.shared.u64 t, %1; cvt.u32.u64 %0, t; }"
        : "=r"(a) : "l"(p));
    return a;
}
__device__ __forceinline__ uint32_t sw64(uint32_t off) {
    return off ^ ((off >> 3) & 0x30);
}
__device__ __forceinline__ void ldsm_x4(uint32_t* r, uint32_t addr) {
    asm volatile("ldmatrix.sync.aligned.m8n8.x4.shared.b16 {%0,%1,%2,%3}, [%4];"
                 : "=r"(r[0]), "=r"(r[1]), "=r"(r[2]), "=r"(r[3]) : "r"(addr));
}
__device__ __forceinline__ void mma_bf16(float* d, const uint32_t* a,
                                         uint32_t b0, uint32_t b1) {
    asm volatile(
        "mma.sync.aligned.m16n8k16.row.col.f32.bf16.bf16.f32 "
        "{%0,%1,%2,%3}, {%4,%5,%6,%7}, {%8,%9}, {%0,%1,%2,%3};"
        : "+f"(d[0]), "+f"(d[1]), "+f"(d[2]), "+f"(d[3])
        : "r"(a[0]), "r"(a[1]), "r"(a[2]), "r"(a[3]), "r"(b0), "r"(b1));
}
__device__ __forceinline__ void cpa16(uint32_t d, const void* s) {
    asm volatile("cp.async.cg.shared.global [%0], [%1], 16;" :: "r"(d), "l"(s));
}
#define CP_COMMIT() asm volatile("cp.async.commit_group;" ::: "memory")
#define CP_WAIT1()  asm volatile("cp.async.wait_group 1;" ::: "memory")
#define CP_WAIT0()  asm volatile("cp.async.wait_group 0;" ::: "memory")

// ---------------- 3xBF16 pipelined segmented GEMM ---------------------------
// C[gm, n0..n0+128) = act(A[row(gm),:] @ B_e^T + bias_e)
// A: bf16 hi/lo [rows][K]; B: bf16 hi/lo [E][N][K] (pre-transposed).
// CTA tile 128Mx128N, K-chunk 32, 256 threads (4M x 2N warps), 3-stage cp.async,
// 2 CTAs/SM. smem rows 64B with SW64 swizzle.
#define TM 128
#define TN 128
#define TK 32
#define O_AH   0                 // 128*32*2 = 8192 bytes per half
#define O_AL   8192
#define O_BH   16384
#define O_BL   24576
#define STG_SZ 32768
#define SMEM_SZ (3 * STG_SZ)     // 98304

__global__ __launch_bounds__(256, 2) void moe_bf16_gemm3(
    const __nv_bfloat16* __restrict__ Ah, const __nv_bfloat16* __restrict__ Al,
    const __nv_bfloat16* __restrict__ Bh, const __nv_bfloat16* __restrict__ Bl,
    const float* __restrict__ bias,
    __nv_bfloat16* __restrict__ Ch, __nv_bfloat16* __restrict__ Cl,
    float* __restrict__ Cf,
    const int* __restrict__ rowmap,
    const int* __restrict__ seg_off,
    const int* __restrict__ seg_cnt,
    int K, int N, int relu)
{
    extern __shared__ char smem[];
    const int e    = blockIdx.z;
    const int mseg = seg_off[e];
    const int mend = mseg + seg_cnt[e];
    const int m0   = mseg + blockIdx.y * TM;
    if (m0 >= mend) return;
    const int n0 = blockIdx.x * TN;

    const long wbase = (long)e * (long)N * (long)K;
    const __nv_bfloat16* Bhe = Bh + wbase;
    const __nv_bfloat16* Ble = Bl + wbase;
    const float* bvec = bias + (long)e * N;

    const uint32_t sb = smem_u32(smem);
    const int tid  = threadIdx.x;
    const int wid  = tid >> 5;
    const int lane = tid & 31;
    const int wm   = wid & 3;      // 4 M-warps x 32 rows
    const int wn   = wid >> 2;     // 2 N-warps x 64 cols

    float acc[16][4];
#pragma unroll
    for (int i = 0; i < 16; i++)
#pragma unroll
        for (int j = 0; j < 4; j++) acc[i][j] = 0.f;

    const int lr = ((lane >> 3) & 1) * 8 + (lane & 7);
    const int lc = (lane >> 4) * 16;

    // precompute per-thread load indices (same each chunk)
    // A: 1024 16B chunks (hi+lo), 4 per thread; B: same
    const int nk = K / TK;

    // ---- loader lambda-ish macro
#define LOAD_CHUNK(kc_)                                                       \
    do {                                                                      \
        const uint32_t base_ = sb + ((kc_) % 3) * STG_SZ;                     \
        const int kbase_ = (kc_) * TK;                                        \
        _Pragma("unroll")                                                     \
        for (int i = 0; i < 4; i++) {                                         \
            int u    = tid + i * 256;                                         \
            int half = u >> 9;                                                \
            int v    = u & 511;                                               \
            int r    = v >> 2;                                                \
            int c    = v & 3;                                                 \
            int gm = m0 + r;                                                  \
            if (gm >= mend) gm = mend - 1;                                    \
            int src = rowmap ? rowmap[gm] : gm;                               \
            const __nv_bfloat16* g = (half ? Al : Ah) + (long)src * K + kbase_ + c * 8; \
            uint32_t d = base_ + (half ? O_AL : O_AH) + sw64((uint32_t)(r * 64 + c * 16)); \
            cpa16(d, g);                                                      \
        }                                                                     \
        _Pragma("unroll")                                                     \
        for (int i = 0; i < 4; i++) {                                         \
            int u    = tid + i * 256;                                         \
            int half = u >> 9;                                                \
            int v    = u & 511;                                               \
            int r    = v >> 2;                                                \
            int c    = v & 3;                                                 \
            const __nv_bfloat16* g = (half ? Ble : Bhe) + (long)(n0 + r) * K + kbase_ + c * 8; \
            uint32_t d = base_ + (half ? O_BL : O_BH) + sw64((uint32_t)(r * 64 + c * 16)); \
            cpa16(d, g);                                                      \
        }                                                                     \
        CP_COMMIT();                                                          \
    } while (0)

    // prologue: stages 0,1
    LOAD_CHUNK(0);
    if (nk > 1) LOAD_CHUNK(1);

    for (int kc = 0; kc < nk; kc++) {
        if (kc == nk - 1) { CP_WAIT0(); } else { CP_WAIT1(); }
        __syncthreads();
        if (kc + 2 < nk) LOAD_CHUNK(kc + 2);

        const uint32_t base = sb + (kc % 3) * STG_SZ;
#pragma unroll
        for (int ks = 0; ks < 2; ks++) {
            const int kb = ks * 32 + lc;
            uint32_t ahf[2][4], alf[2][4], bfrag[4][4];
#pragma unroll
            for (int mt = 0; mt < 2; mt++) {
                uint32_t off = sw64((uint32_t)((wm * 32 + mt * 16 + lr) * 64 + kb));
                ldsm_x4(ahf[mt], base + O_AH + off);
                ldsm_x4(alf[mt], base + O_AL + off);
            }
#pragma unroll
            for (int nt = 0; nt < 4; nt++) {
                uint32_t off = sw64((uint32_t)((wn * 64 + nt * 16 + lr) * 64 + kb));
                ldsm_x4(bfrag[nt], base + O_BH + off);
            }
#pragma unroll
            for (int mt = 0; mt < 2; mt++)
#pragma unroll
                for (int nt = 0; nt < 4; nt++) {
                    mma_bf16(acc[mt * 8 + nt * 2 + 0], ahf[mt], bfrag[nt][0], bfrag[nt][2]);
                    mma_bf16(acc[mt * 8 + nt * 2 + 1], ahf[mt], bfrag[nt][1], bfrag[nt][3]);
                    mma_bf16(acc[mt * 8 + nt * 2 + 0], alf[mt], bfrag[nt][0], bfrag[nt][2]);
                    mma_bf16(acc[mt * 8 + nt * 2 + 1], alf[mt], bfrag[nt][1], bfrag[nt][3]);
                }
#pragma unroll
            for (int nt = 0; nt < 4; nt++) {
                uint32_t off = sw64((uint32_t)((wn * 64 + nt * 16 + lr) * 64 + kb));
                ldsm_x4(bfrag[nt], base + O_BL + off);
            }
#pragma unroll
            for (int mt = 0; mt < 2; mt++)
#pragma unroll
                for (int nt = 0; nt < 4; nt++) {
                    mma_bf16(acc[mt * 8 + nt * 2 + 0], ahf[mt], bfrag[nt][0], bfrag[nt][2]);
                    mma_bf16(acc[mt * 8 + nt * 2 + 1], ahf[mt], bfrag[nt][1], bfrag[nt][3]);
                }
        }
    }
#undef LOAD_CHUNK

    // ---- epilogue: bias + relu, then either split bf16 hi/lo or fp32 store
#pragma unroll
    for (int mt = 0; mt < 2; mt++) {
#pragma unroll
        for (int nt = 0; nt < 8; nt++) {
            const float* a4 = acc[mt * 8 + nt];
            int col  = n0 + wn * 64 + nt * 8 + ((lane & 3) << 1);
            float bb0 = bvec[col], bb1 = bvec[col + 1];
            int row0 = m0 + wm * 32 + mt * 16 + (lane >> 2);
            int row1 = row0 + 8;
            float v0 = a4[0] + bb0, v1 = a4[1] + bb1;
            float v2 = a4[2] + bb0, v3 = a4[3] + bb1;
            if (relu) {
                v0 = fmaxf(v0, 0.f); v1 = fmaxf(v1, 0.f);
                v2 = fmaxf(v2, 0.f); v3 = fmaxf(v3, 0.f);
            }
            if (Cf) {
                if (row0 < mend)
                    *reinterpret_cast<float2*>(Cf + (long)row0 * N + col) = make_float2(v0, v1);
                if (row1 < mend)
                    *reinterpret_cast<float2*>(Cf + (long)row1 * N + col) = make_float2(v2, v3);
            } else {
                if (row0 < mend) {
                    __nv_bfloat162 h, l;
                    h.x = __float2bfloat16(v0); h.y = __float2bfloat16(v1);
                    l.x = __float2bfloat16(v0 - __bfloat162float(h.x));
                    l.y = __float2bfloat16(v1 - __bfloat162float(h.y));
                    *reinterpret_cast<uint32_t*>(Ch + (long)row0 * N + col) = *reinterpret_cast<uint32_t*>(&h);
                    *reinterpret_cast<uint32_t*>(Cl + (long)row0 * N + col) = *reinterpret_cast<uint32_t*>(&l);
                }
                if (row1 < mend) {
                    __nv_bfloat162 h, l;
                    h.x = __float2bfloat16(v2); h.y = __float2bfloat16(v3);
                    l.x = __float2bfloat16(v2 - __bfloat162float(h.x));
                    l.y = __float2bfloat16(v3 - __bfloat162float(h.y));
                    *reinterpret_cast<uint32_t*>(Ch + (long)row1 * N + col) = *reinterpret_cast<uint32_t*>(&h);
                    *reinterpret_cast<uint32_t*>(Cl + (long)row1 * N + col) = *reinterpret_cast<uint32_t*>(&l);
                }
            }
        }
    }
}

// ---------------- split / transpose pre-passes ------------------------------
__global__ __launch_bounds__(256) void k_splitx(const float* __restrict__ x)
{
    long i = (long)(blockIdx.x * 256 + threadIdx.x) * 4;
    if (i >= (long)BQ * DQ) return;
    float4 v = *reinterpret_cast<const float4*>(x + i);
    __nv_bfloat162 h0, l0, h1, l1;
    h0.x = __float2bfloat16(v.x); h0.y = __float2bfloat16(v.y);
    l0.x = __float2bfloat16(v.x - __bfloat162float(h0.x));
    l0.y = __float2bfloat16(v.y - __bfloat162float(h0.y));
    h1.x = __float2bfloat16(v.z); h1.y = __float2bfloat16(v.w);
    l1.x = __float2bfloat16(v.z - __bfloat162float(h1.x));
    l1.y = __float2bfloat16(v.w - __bfloat162float(h1.y));
    *reinterpret_cast<uint2*>(g_xh + i) = make_uint2(
        *reinterpret_cast<uint32_t*>(&h0), *reinterpret_cast<uint32_t*>(&h1));
    *reinterpret_cast<uint2*>(g_xl + i) = make_uint2(
        *reinterpret_cast<uint32_t*>(&l0), *reinterpret_cast<uint32_t*>(&l1));
}

// W [E][K][N] f32 -> Wh/Wl [E][N][K] bf16
__global__ __launch_bounds__(256) void k_splitw(
    const float* __restrict__ src, __nv_bfloat16* __restrict__ dh,
    __nv_bfloat16* __restrict__ dl, int K, int N)
{
    __shared__ float t[32][33];
    const int e  = blockIdx.z;
    const int n0 = blockIdx.x * 32;
    const int k0 = blockIdx.y * 32;
    const int tx = threadIdx.x & 31;
    const int ty = threadIdx.x >> 5;  // 0..7
    const float* S = src + (long)e * K * N;
    const long ob  = (long)e * N * K;
#pragma unroll
    for (int i = 0; i < 32; i += 8)
        t[ty + i][tx] = S[(long)(k0 + ty + i) * N + n0 + tx];
    __syncthreads();
#pragma unroll
    for (int i = 0; i < 32; i += 8) {
        float v = t[tx][ty + i];
        __nv_bfloat16 h = __float2bfloat16(v);
        __nv_bfloat16 l = __float2bfloat16(v - __bfloat162float(h));
        long o = ob + (long)(n0 + ty + i) * K + k0 + tx;
        dh[o] = h;
        dl[o] = l;
    }
}

// ---------------- fp32 SGEMM (gate layer 1 only) ---------------------------
__global__ __launch_bounds__(256) void sgemm_seg(
    const float* __restrict__ A,
    const float* __restrict__ Wbase,
    const float* __restrict__ bias,
    float* __restrict__ C,
    const int* __restrict__ seg_off,
    const int* __restrict__ seg_cnt,
    int K, int N, int relu)
{
    const int e    = blockIdx.z;
    const int mseg = seg_off[e];
    const int mend = mseg + seg_cnt[e];
    const int m0   = mseg + blockIdx.y * 128;
    if (m0 >= mend) return;
    const int n0 = blockIdx.x * 128;

    const float* W    = Wbase;
    const float* bvec = bias;

    __shared__ float Ast[16][128];
    __shared__ float Bs [16][128];

    const int tid = threadIdx.x;
    const int tx  = tid & 15;
    const int ty  = tid >> 4;

    float acc[8][8];
#pragma unroll
    for (int m = 0; m < 8; m++)
#pragma unroll
        for (int n = 0; n < 8; n++) acc[m][n] = 0.f;

    for (int k0 = 0; k0 < K; k0 += 16) {
#pragma unroll
        for (int i = 0; i < 2; i++) {
            int q  = tid + i * 256;
            int r  = q >> 2;
            int c4 = q & 3;
            int gm = m0 + r;
            float4 v = make_float4(0.f, 0.f, 0.f, 0.f);
            if (gm < mend)
                v = *reinterpret_cast<const float4*>(A + (long)gm * K + k0 + c4 * 4);
            Ast[c4 * 4 + 0][r] = v.x;
            Ast[c4 * 4 + 1][r] = v.y;
            Ast[c4 * 4 + 2][r] = v.z;
            Ast[c4 * 4 + 3][r] = v.w;
        }
#pragma unroll
        for (int i = 0; i < 2; i++) {
            int q  = tid + i * 256;
            int r  = q >> 5;
            int c4 = q & 31;
            float4 v = *reinterpret_cast<const float4*>(W + (long)(k0 + r) * N + n0 + c4 * 4);
            *reinterpret_cast<float4*>(&Bs[r][c4 * 4]) = v;
        }
        __syncthreads();

#pragma unroll
        for (int kk = 0; kk < 16; kk++) {
            float4 a0 = *reinterpret_cast<const float4*>(&Ast[kk][ty * 8]);
            float4 a1 = *reinterpret_cast<const float4*>(&Ast[kk][ty * 8 + 4]);
            float4 b0 = *reinterpret_cast<const float4*>(&Bs[kk][tx * 8]);
            float4 b1 = *reinterpret_cast<const float4*>(&Bs[kk][tx * 8 + 4]);
            float ra[8] = {a0.x, a0.y, a0.z, a0.w, a1.x, a1.y, a1.z, a1.w};
            float rb[8] = {b0.x, b0.y, b0.z, b0.w, b1.x, b1.y, b1.z, b1.w};
#pragma unroll
            for (int m = 0; m < 8; m++)
#pragma unroll
                for (int n = 0; n < 8; n++) acc[m][n] = fmaf(ra[m], rb[n], acc[m][n]);
        }
        __syncthreads();
    }

#pragma unroll
    for (int m = 0; m < 8; m++) {
        int gm = m0 + ty * 8 + m;
        if (gm >= mend) continue;
        float* crow = C + (long)gm * N;
#pragma unroll
        for (int n = 0; n < 8; n++) {
            int gn = n0 + tx * 8 + n;
            float v = acc[m][n] + bvec[gn];
            if (relu) v = fmaxf(v, 0.f);
            crow[gn] = v;
        }
    }
}

// ---------------- small kernels ------------------------------------------
__global__ void k_zero()
{
    int t = threadIdx.x;
    if (t < EQ) { g_cnt[t] = 0; g_cursor[t] = 0; }
}

__global__ __launch_bounds__(128) void k_gate2(const float* __restrict__ Wg2,
                                               const float* __restrict__ bg2)
{
    int b    = blockIdx.x * 4 + (threadIdx.x >> 5);
    int lane = threadIdx.x & 31;
    const float* grow = g_g + (long)b * GQ;

    float acc[8] = {0, 0, 0, 0, 0, 0, 0, 0};
    for (int k = lane; k < GQ; k += 32) {
        float gv = grow[k];
        const float* w = Wg2 + k * 8;
#pragma unroll
        for (int e = 0; e < 8; e++) acc[e] = fmaf(gv, w[e], acc[e]);
    }
#pragma unroll
    for (int e = 0; e < 8; e++) {
#pragma unroll
        for (int o = 16; o; o >>= 1) acc[e] += __shfl_xor_sync(0xffffffffu, acc[e], o);
    }
    if (lane == 0) {
        float l[8], m = -1e30f;
#pragma unroll
        for (int e = 0; e < 8; e++) { l[e] = acc[e] + bg2[e]; m = fmaxf(m, l[e]); }
        float s = 0.f;
#pragma unroll
        for (int e = 0; e < 8; e++) { l[e] = expf(l[e] - m); s += l[e]; }
        float inv = 1.f / s;
#pragma unroll
        for (int e = 0; e < 8; e++) { l[e] *= inv; g_gatew[b * 8 + e] = l[e]; }
        int i0 = 0;
#pragma unroll
        for (int e = 1; e < 8; e++) if (l[e] > l[i0]) i0 = e;
        int i1 = -1;
#pragma unroll
        for (int e = 0; e < 8; e++) {
            if (e == i0) continue;
            if (i1 < 0 || l[e] > l[i1]) i1 = e;
        }
        float w0 = l[i0], w1 = l[i1];
        float mm = fmaxf(w0, w1);
        float e0 = expf(w0 - mm), e1 = expf(w1 - mm);
        float si = 1.f / (e0 + e1);
        g_topidx[2 * b]     = i0;
        g_topidx[2 * b + 1] = i1;
        g_topw[2 * b]       = e0 * si;
        g_topw[2 * b + 1]   = e1 * si;
        atomicAdd(&g_cnt[i0], 1);
        atomicAdd(&g_cnt[i1], 1);
    }
}

__global__ void k_offsets()
{
    if (threadIdx.x == 0) {
        int s = 0;
        for (int e = 0; e < EQ; e++) { g_off[e] = s; s += g_cnt[e]; }
        g_off[EQ] = s;
    }
}

__global__ void k_scatter()
{
    int b = blockIdx.x * blockDim.x + threadIdx.x;
    if (b >= BQ) return;
#pragma unroll
    for (int s = 0; s < 2; s++) {
        int e = g_topidx[2 * b + s];
        int p = g_off[e] + atomicAdd(&g_cursor[e], 1);
        g_ptok[p]         = b;
        g_pidx[2 * b + s] = p;
    }
}

__global__ __launch_bounds__(256) void k_usage()
{
    int e = blockIdx.x, t = threadIdx.x;
    __shared__ float sh[256];
    float s = 0.f;
    for (int b = t; b < BQ; b += 256) s += g_gatew[b * 8 + e];
    sh[t] = s;
    __syncthreads();
    for (int o = 128; o; o >>= 1) {
        if (t < o) sh[t] += sh[t + o];
        __syncthreads();
    }
    if (t == 0) g_usage[e] = sh[0];
}

__global__ void k_loss(float* out, int out_size)
{
    if (threadIdx.x == 0 && out_size > BQ * DOUTQ) {
        float acc = 0.f;
        for (int e = 0; e < EQ; e++) {
            float d = g_usage[e] / (float)BQ - 1.0f / (float)EQ;
            acc += d * d;
        }
        out[BQ * DOUTQ] = acc / (float)EQ;
    }
}

__global__ __launch_bounds__(256) void k_combine(float* __restrict__ out)
{
    int b  = blockIdx.x;
    int p0 = g_pidx[2 * b], p1 = g_pidx[2 * b + 1];
    float w0 = g_topw[2 * b], w1 = g_topw[2 * b + 1];
    const float* y0 = g_y + (long)p0 * DOUTQ;
    const float* y1 = g_y + (long)p1 * DOUTQ;
    float* o = out + (long)b * DOUTQ;
    for (int d = threadIdx.x; d < DOUTQ; d += 256)
        o[d] = w0 * y0[d] + w1 * y1[d];
}

// ---------------- launch --------------------------------------------------
extern "C" void kernel_launch(void* const* d_in, const int* in_sizes, int n_in,
                              void* d_out, int out_size)
{
    const float* x   = (const float*)d_in[0];
    const float* W1  = (const float*)d_in[1];
    const float* b1  = (const float*)d_in[2];
    const float* W2  = (const float*)d_in[3];
    const float* b2  = (const float*)d_in[4];
    const float* W3  = (const float*)d_in[5];
    const float* b3  = (const float*)d_in[6];
    const float* Wg1 = (const float*)d_in[7];
    const float* bg1 = (const float*)d_in[8];
    const float* Wg2 = (const float*)d_in[9];
    const float* bg2 = (const float*)d_in[10];
    float* out = (float*)d_out;

    float* p_g;
    float* p_y;
    int *p_goff, *p_gcnt, *p_off, *p_cnt, *p_ptok;
    __nv_bfloat16 *p_xh, *p_xl, *p_w1h, *p_w1l, *p_w2h, *p_w2l, *p_w3h, *p_w3l;
    __nv_bfloat16 *p_h1h, *p_h1l, *p_h2h, *p_h2l;
    cudaGetSymbolAddress((void**)&p_g,    g_g);
    cudaGetSymbolAddress((void**)&p_y,    g_y);
    cudaGetSymbolAddress((void**)&p_goff, g_gate_off);
    cudaGetSymbolAddress((void**)&p_gcnt, g_gate_cnt);
    cudaGetSymbolAddress((void**)&p_off,  g_off);
    cudaGetSymbolAddress((void**)&p_cnt,  g_cnt);
    cudaGetSymbolAddress((void**)&p_ptok, g_ptok);
    cudaGetSymbolAddress((void**)&p_xh,   g_xh);
    cudaGetSymbolAddress((void**)&p_xl,   g_xl);
    cudaGetSymbolAddress((void**)&p_w1h,  g_w1h);
    cudaGetSymbolAddress((void**)&p_w1l,  g_w1l);
    cudaGetSymbolAddress((void**)&p_w2h,  g_w2h);
    cudaGetSymbolAddress((void**)&p_w2l,  g_w2l);
    cudaGetSymbolAddress((void**)&p_w3h,  g_w3h);
    cudaGetSymbolAddress((void**)&p_w3l,  g_w3l);
    cudaGetSymbolAddress((void**)&p_h1h,  g_h1h);
    cudaGetSymbolAddress((void**)&p_h1l,  g_h1l);
    cudaGetSymbolAddress((void**)&p_h2h,  g_h2h);
    cudaGetSymbolAddress((void**)&p_h2l,  g_h2l);

    cudaFuncSetAttribute(moe_bf16_gemm3,
                         cudaFuncAttributeMaxDynamicSharedMemorySize, SMEM_SZ);

    k_zero<<<1, 32>>>();

    // pre-split x and weights (hi/lo bf16, W transposed to [E][N][K])
    k_splitx<<<(BQ * DQ / 4 + 255) / 256, 256>>>(x);
    {
        dim3 g1(HQ / 32, DQ / 32, EQ);
        k_splitw<<<g1, 256>>>(W1, p_w1h, p_w1l, DQ, HQ);
        dim3 g2(H2Q / 32, HQ / 32, EQ);
        k_splitw<<<g2, 256>>>(W2, p_w2h, p_w2l, HQ, H2Q);
        dim3 g3(DOUTQ / 32, H2Q / 32, EQ);
        k_splitw<<<g3, 256>>>(W3, p_w3h, p_w3l, H2Q, DOUTQ);
    }

    // gate: g = relu(x @ Wg1 + bg1) then layer2 + softmax + top2 + routing
    {
        dim3 grid(GQ / 128, BQ / 128, 1);
        sgemm_seg<<<grid, 256>>>(x, Wg1, bg1, p_g, p_goff, p_gcnt, DQ, GQ, 1);
    }
    k_gate2<<<BQ / 4, 128>>>(Wg2, bg2);
    k_offsets<<<1, 32>>>();
    k_scatter<<<BQ / 256, 256>>>();
    k_usage<<<EQ, 256>>>();
    k_loss<<<1, 32>>>(out, out_size);

    // expert layer 1: h1 = relu(gather(x) @ W1[e] + b1[e])  K=1024, N=4096
    {
        dim3 grid(HQ / TN, PAIRS / TM, EQ);
        moe_bf16_gemm3<<<grid, 256, SMEM_SZ>>>(
            p_xh, p_xl, p_w1h, p_w1l, b1, p_h1h, p_h1l, nullptr,
            p_ptok, p_off, p_cnt, DQ, HQ, 1);
    }
    // expert layer 2: h2 = relu(h1 @ W2[e] + b2[e])  K=4096, N=2048
    {
        dim3 grid(H2Q / TN, PAIRS / TM, EQ);
        moe_bf16_gemm3<<<grid, 256, SMEM_SZ>>>(
            p_h1h, p_h1l, p_w2h, p_w2l, b2, p_h2h, p_h2l, nullptr,
            nullptr, p_off, p_cnt, HQ, H2Q, 1);
    }
    // expert layer 3: y = h2 @ W3[e] + b3[e]  K=2048, N=1024
    {
        dim3 grid(DOUTQ / TN, PAIRS / TM, EQ);
        moe_bf16_gemm3<<<grid, 256, SMEM_SZ>>>(
            p_h2h, p_h2l, p_w3h, p_w3l, b3, nullptr, nullptr, p_y,
            nullptr, p_off, p_cnt, H2Q, DOUTQ, 0);
    }
    k_combine<<<BQ, 256>>>(out);
}